// round 2
// baseline (speedup 1.0000x reference)
#include <cuda_runtime.h>
#include <math.h>

#define Bc   4
#define Nc   8192
#define Gc   512
#define Ec   512
#define Dc   1536
#define Mtot (Bc * Nc)   // 32768

// ---- scratch (static __device__ arrays; no allocation allowed) ----
__device__ float g_interp[Mtot * Dc];     // [32768, 1536]
__device__ float g_h1[Mtot * 512];        // [32768, 512]
__device__ int   g_idx[Mtot * 3];
__device__ float g_wts[Mtot * 3];
__device__ float g_s1[512], g_t1[512], g_s2[512], g_t2[512];

// ---------------------------------------------------------------------------
// Fold BatchNorm(eval) into per-channel scale/bias: y = x*s + t
// ---------------------------------------------------------------------------
__global__ void prep_kernel(const float* __restrict__ b1, const float* __restrict__ g1,
                            const float* __restrict__ be1, const float* __restrict__ m1,
                            const float* __restrict__ v1,
                            const float* __restrict__ b2, const float* __restrict__ g2,
                            const float* __restrict__ be2, const float* __restrict__ m2,
                            const float* __restrict__ v2) {
    int i = threadIdx.x;
    if (i < 512) {
        float s = g1[i] * rsqrtf(v1[i] + 1e-5f);
        g_s1[i] = s;
        g_t1[i] = (b1[i] - m1[i]) * s + be1[i];
        float s2 = g2[i] * rsqrtf(v2[i] + 1e-5f);
        g_s2[i] = s2;
        g_t2[i] = (b2[i] - m2[i]) * s2 + be2[i];
    }
}

// ---------------------------------------------------------------------------
// 3-NN with bit-exact emulation of the reference's fp32 arithmetic:
//   xx = (x0*x0 + x1*x1) + x2*x2            (separate muls, sequential adds)
//   cc = (c0*c0 + c1*c1) + c2*c2
//   dot = fma(x2,c2, fma(x1,c1, x0*c0))     (dot_general K=3 fma chain)
//   d   = (xx + cc) - 2*dot                 (separate elementwise ops)
// All via explicit round-to-nearest intrinsics so nvcc cannot re-contract.
// ---------------------------------------------------------------------------
__global__ void knn_kernel(const float* __restrict__ xyz,
                           const float* __restrict__ centers) {
    __shared__ float4 sc[Gc];   // cx, cy, cz, cc
    int p = blockIdx.x * blockDim.x + threadIdx.x;
    int b = p >> 13;            // N = 8192
    for (int g = threadIdx.x; g < Gc; g += blockDim.x) {
        float cx = centers[(b * Gc + g) * 3 + 0];
        float cy = centers[(b * Gc + g) * 3 + 1];
        float cz = centers[(b * Gc + g) * 3 + 2];
        float cc = __fadd_rn(__fadd_rn(__fmul_rn(cx, cx), __fmul_rn(cy, cy)),
                             __fmul_rn(cz, cz));
        sc[g] = make_float4(cx, cy, cz, cc);
    }
    __syncthreads();

    float x = xyz[p * 3 + 0], y = xyz[p * 3 + 1], z = xyz[p * 3 + 2];
    float xx = __fadd_rn(__fadd_rn(__fmul_rn(x, x), __fmul_rn(y, y)),
                         __fmul_rn(z, z));

    float d0 = INFINITY, d1 = INFINITY, d2 = INFINITY;
    int   i0 = 0, i1 = 0, i2 = 0;
    for (int g = 0; g < Gc; g++) {
        float4 c = sc[g];
        float dot = __fmaf_rn(z, c.z, __fmaf_rn(y, c.y, __fmul_rn(x, c.x)));
        float d   = __fsub_rn(__fadd_rn(xx, c.w), __fmul_rn(2.0f, dot));
        if (d < d0)      { d2 = d1; i2 = i1; d1 = d0; i1 = i0; d0 = d; i0 = g; }
        else if (d < d1) { d2 = d1; i2 = i1; d1 = d;  i1 = g; }
        else if (d < d2) { d2 = d;  i2 = g; }
    }
    // weights exactly as reference: r = 1/(d+1e-8); w = r / ((r0+r1)+r2)
    float r0 = __fdiv_rn(1.0f, __fadd_rn(d0, 1e-8f));
    float r1 = __fdiv_rn(1.0f, __fadd_rn(d1, 1e-8f));
    float r2 = __fdiv_rn(1.0f, __fadd_rn(d2, 1e-8f));
    float rs = __fadd_rn(__fadd_rn(r0, r1), r2);
    g_idx[p * 3 + 0] = i0; g_idx[p * 3 + 1] = i1; g_idx[p * 3 + 2] = i2;
    g_wts[p * 3 + 0] = __fdiv_rn(r0, rs);
    g_wts[p * 3 + 1] = __fdiv_rn(r1, rs);
    g_wts[p * 3 + 2] = __fdiv_rn(r2, rs);
}

// ---------------------------------------------------------------------------
// Interpolation: interp[p,d] = fma(w2,f2, fma(w1,f1, w0*f0))  (k=3 fma chain)
// ---------------------------------------------------------------------------
__global__ void interp_kernel(const float4* __restrict__ H4,
                              const float4* __restrict__ H8,
                              const float4* __restrict__ H12) {
    int gid = blockIdx.x * blockDim.x + threadIdx.x;   // < Mtot * 384
    int p   = gid / 384;
    int c4  = gid - p * 384;
    int seg = c4 >> 7;
    int off = c4 & 127;
    const float4* H = (seg == 0) ? H4 : ((seg == 1) ? H8 : H12);
    int b = p >> 13;
    int i0 = g_idx[p * 3 + 0], i1 = g_idx[p * 3 + 1], i2 = g_idx[p * 3 + 2];
    float w0 = g_wts[p * 3 + 0], w1 = g_wts[p * 3 + 1], w2 = g_wts[p * 3 + 2];
    float4 f0 = H[(b * Gc + i0) * 128 + off];
    float4 f1 = H[(b * Gc + i1) * 128 + off];
    float4 f2 = H[(b * Gc + i2) * 128 + off];
    float4 o;
    o.x = __fmaf_rn(w2, f2.x, __fmaf_rn(w1, f1.x, __fmul_rn(w0, f0.x)));
    o.y = __fmaf_rn(w2, f2.y, __fmaf_rn(w1, f1.y, __fmul_rn(w0, f0.y)));
    o.z = __fmaf_rn(w2, f2.z, __fmaf_rn(w1, f1.z, __fmul_rn(w0, f0.z)));
    o.w = __fmaf_rn(w2, f2.w, __fmaf_rn(w1, f1.w, __fmul_rn(w0, f0.w)));
    reinterpret_cast<float4*>(g_interp)[gid] = o;
}

// ---------------------------------------------------------------------------
// SGEMM + fused BN(eval) + ReLU.
//   C[M,512] = relu( (A[M,K] @ W^T) * scale + bias ),  W is [512, K] row-major
// Tiles: BM=128, BN=64, BK=16; 256 threads; 8x4 per-thread microtile.
// ---------------------------------------------------------------------------
template <int K, int LAYER>
__global__ __launch_bounds__(256) void gemm_bn_relu(const float* __restrict__ W,
                                                    float* __restrict__ Cext) {
    __shared__ float As[16][128];
    __shared__ float Bs[16][64];

    const float* A     = (LAYER == 1) ? g_interp : g_h1;
    float*       C     = (LAYER == 1) ? g_h1     : Cext;
    const float* scale = (LAYER == 1) ? g_s1     : g_s2;
    const float* bias  = (LAYER == 1) ? g_t1     : g_t2;

    int tid = threadIdx.x;
    int tx  = tid & 15;
    int ty  = tid >> 4;
    int m0  = blockIdx.y * 128;
    int n0  = blockIdx.x * 64;

    const float* Ab = A + (size_t)m0 * K;
    const float* Wb = W + (size_t)n0 * K;

    float acc[8][4];
#pragma unroll
    for (int i = 0; i < 8; i++)
#pragma unroll
        for (int j = 0; j < 4; j++) acc[i][j] = 0.0f;

    for (int k0 = 0; k0 < K; k0 += 16) {
#pragma unroll
        for (int it = 0; it < 2; it++) {
            int id = tid + it * 256;
            int ar = id >> 2;
            int ac = (id & 3) << 2;
            float4 v = *reinterpret_cast<const float4*>(&Ab[(size_t)ar * K + k0 + ac]);
            As[ac + 0][ar] = v.x; As[ac + 1][ar] = v.y;
            As[ac + 2][ar] = v.z; As[ac + 3][ar] = v.w;
        }
        {
            int br = tid >> 2;
            int bc = (tid & 3) << 2;
            float4 v = *reinterpret_cast<const float4*>(&Wb[(size_t)br * K + k0 + bc]);
            Bs[bc + 0][br] = v.x; Bs[bc + 1][br] = v.y;
            Bs[bc + 2][br] = v.z; Bs[bc + 3][br] = v.w;
        }
        __syncthreads();

#pragma unroll
        for (int kk = 0; kk < 16; kk++) {
            float4 b4 = *reinterpret_cast<const float4*>(&Bs[kk][tx << 2]);
            float4 a0 = *reinterpret_cast<const float4*>(&As[kk][ty << 3]);
            float4 a1 = *reinterpret_cast<const float4*>(&As[kk][(ty << 3) + 4]);
            float a[8] = {a0.x, a0.y, a0.z, a0.w, a1.x, a1.y, a1.z, a1.w};
            float bb[4] = {b4.x, b4.y, b4.z, b4.w};
#pragma unroll
            for (int i = 0; i < 8; i++)
#pragma unroll
                for (int j = 0; j < 4; j++)
                    acc[i][j] = fmaf(a[i], bb[j], acc[i][j]);
        }
        __syncthreads();
    }

    int n = n0 + (tx << 2);
    float4 sc4 = *reinterpret_cast<const float4*>(&scale[n]);
    float4 bi4 = *reinterpret_cast<const float4*>(&bias[n]);
#pragma unroll
    for (int i = 0; i < 8; i++) {
        int m = m0 + (ty << 3) + i;
        float4 o;
        o.x = fmaxf(fmaf(acc[i][0], sc4.x, bi4.x), 0.0f);
        o.y = fmaxf(fmaf(acc[i][1], sc4.y, bi4.y), 0.0f);
        o.z = fmaxf(fmaf(acc[i][2], sc4.z, bi4.z), 0.0f);
        o.w = fmaxf(fmaf(acc[i][3], sc4.w, bi4.w), 0.0f);
        *reinterpret_cast<float4*>(&C[(size_t)m * 512 + n]) = o;
    }
}

// ---------------------------------------------------------------------------
extern "C" void kernel_launch(void* const* d_in, const int* in_sizes, int n_in,
                              void* d_out, int out_size) {
    (void)in_sizes; (void)n_in; (void)out_size;
    const float* xyz     = (const float*)d_in[0];
    const float* centers = (const float*)d_in[1];
    const float* H4      = (const float*)d_in[2];
    const float* H8      = (const float*)d_in[3];
    const float* H12     = (const float*)d_in[4];
    const float* w1      = (const float*)d_in[5];
    const float* b1      = (const float*)d_in[6];
    const float* g1      = (const float*)d_in[7];
    const float* be1     = (const float*)d_in[8];
    const float* m1      = (const float*)d_in[9];
    const float* v1      = (const float*)d_in[10];
    const float* w2      = (const float*)d_in[11];
    const float* b2      = (const float*)d_in[12];
    const float* g2      = (const float*)d_in[13];
    const float* be2     = (const float*)d_in[14];
    const float* m2      = (const float*)d_in[15];
    const float* v2      = (const float*)d_in[16];
    float* out = (float*)d_out;

    prep_kernel<<<1, 512>>>(b1, g1, be1, m1, v1, b2, g2, be2, m2, v2);
    knn_kernel<<<Mtot / 256, 256>>>(xyz, centers);
    interp_kernel<<<(Mtot * 384) / 256, 256>>>(
        (const float4*)H4, (const float4*)H8, (const float4*)H12);

    dim3 grid(512 / 64, Mtot / 128);   // (8, 256)
    gemm_bn_relu<1536, 1><<<grid, 256>>>(w1, nullptr);
    gemm_bn_relu<512, 2><<<grid, 256>>>(w2, out);
}

// round 5
// speedup vs baseline: 2.9064x; 2.9064x over previous
#include <cuda_runtime.h>
#include <cuda_bf16.h>
#include <math.h>
#include <stdint.h>

#define Bc   4
#define Nc   8192
#define Gc   512
#define K1   1536
#define K2   512
#define Mtot (Bc * Nc)   // 32768

// ---------------- scratch (__device__ globals; no allocation allowed) -------
__device__ unsigned short g_Ah[(size_t)Mtot * K1];   // interp hi (bf16 bits)
__device__ unsigned short g_Al[(size_t)Mtot * K1];   // interp lo
__device__ unsigned short g_h1h[(size_t)Mtot * K2];  // hidden hi
__device__ unsigned short g_h1l[(size_t)Mtot * K2];  // hidden lo
__device__ unsigned short g_w1h[512 * K1], g_w1l[512 * K1];
__device__ unsigned short g_w2h[512 * K2], g_w2l[512 * K2];
__device__ int   g_idx[Mtot * 3];
__device__ float g_wts[Mtot * 3];
__device__ float g_s1[512], g_t1[512], g_s2[512], g_t2[512];

// ---------------- helpers ---------------------------------------------------
__device__ __forceinline__ uint32_t smem_u32(const void* p) {
    uint32_t a;
    asm("{ .reg .u64 t; cvta.to.shared.u64 t, %1; cvt.u32.u64 %0, t; }" : "=r"(a) : "l"(p));
    return a;
}
__device__ __forceinline__ void cp_async16(uint32_t dst, const void* src) {
    asm volatile("cp.async.cg.shared.global [%0], [%1], 16;" :: "r"(dst), "l"(src));
}
#define CP_COMMIT() asm volatile("cp.async.commit_group;" ::: "memory")
#define CP_WAIT(n)  asm volatile("cp.async.wait_group %0;" :: "n"(n) : "memory")

__device__ __forceinline__ void ldm_x4(uint32_t* r, uint32_t a) {
    asm volatile("ldmatrix.sync.aligned.m8n8.x4.shared.b16 {%0,%1,%2,%3}, [%4];"
                 : "=r"(r[0]), "=r"(r[1]), "=r"(r[2]), "=r"(r[3]) : "r"(a));
}
__device__ __forceinline__ void mma_bf16(float* c, const uint32_t* a, const uint32_t* b) {
    asm volatile("mma.sync.aligned.m16n8k16.row.col.f32.bf16.bf16.f32 "
                 "{%0,%1,%2,%3}, {%4,%5,%6,%7}, {%8,%9}, {%0,%1,%2,%3};"
                 : "+f"(c[0]), "+f"(c[1]), "+f"(c[2]), "+f"(c[3])
                 : "r"(a[0]), "r"(a[1]), "r"(a[2]), "r"(a[3]), "r"(b[0]), "r"(b[1]));
}
__device__ __forceinline__ uint32_t swz(uint32_t o) { return o ^ ((o >> 3) & 0x70); }

// ---------------------------------------------------------------------------
// prep: BN fold (y = x*s + t)
// ---------------------------------------------------------------------------
__global__ void prep_kernel(const float* __restrict__ b1, const float* __restrict__ g1,
                            const float* __restrict__ be1, const float* __restrict__ m1,
                            const float* __restrict__ v1,
                            const float* __restrict__ b2, const float* __restrict__ g2,
                            const float* __restrict__ be2, const float* __restrict__ m2,
                            const float* __restrict__ v2) {
    int i = threadIdx.x;
    if (i < 512) {
        float s = g1[i] * rsqrtf(v1[i] + 1e-5f);
        g_s1[i] = s;
        g_t1[i] = (b1[i] - m1[i]) * s + be1[i];
        float s2 = g2[i] * rsqrtf(v2[i] + 1e-5f);
        g_s2[i] = s2;
        g_t2[i] = (b2[i] - m2[i]) * s2 + be2[i];
    }
}

// weights -> bf16 hi/lo split
__global__ void convw_kernel(const float* __restrict__ w1, const float* __restrict__ w2) {
    int i = blockIdx.x * 256 + threadIdx.x;
    if (i < 512 * K1) {
        float v = w1[i];
        __nv_bfloat16 h = __float2bfloat16(v);
        __nv_bfloat16 l = __float2bfloat16(v - __bfloat162float(h));
        g_w1h[i] = *(unsigned short*)&h;
        g_w1l[i] = *(unsigned short*)&l;
    }
    if (i < 512 * K2) {
        float v = w2[i];
        __nv_bfloat16 h = __float2bfloat16(v);
        __nv_bfloat16 l = __float2bfloat16(v - __bfloat162float(h));
        g_w2h[i] = *(unsigned short*)&h;
        g_w2l[i] = *(unsigned short*)&l;
    }
}

// ---------------------------------------------------------------------------
// 3-NN: bit-exact emulation of reference fp32 lowering (validated R2)
// ---------------------------------------------------------------------------
__global__ void knn_kernel(const float* __restrict__ xyz,
                           const float* __restrict__ centers) {
    __shared__ float4 sc[Gc];
    int p = blockIdx.x * blockDim.x + threadIdx.x;
    int b = p >> 13;
    for (int g = threadIdx.x; g < Gc; g += blockDim.x) {
        float cx = centers[(b * Gc + g) * 3 + 0];
        float cy = centers[(b * Gc + g) * 3 + 1];
        float cz = centers[(b * Gc + g) * 3 + 2];
        float cc = __fadd_rn(__fadd_rn(__fmul_rn(cx, cx), __fmul_rn(cy, cy)),
                             __fmul_rn(cz, cz));
        sc[g] = make_float4(cx, cy, cz, cc);
    }
    __syncthreads();

    float x = xyz[p * 3 + 0], y = xyz[p * 3 + 1], z = xyz[p * 3 + 2];
    float xx = __fadd_rn(__fadd_rn(__fmul_rn(x, x), __fmul_rn(y, y)),
                         __fmul_rn(z, z));
    float d0 = INFINITY, d1 = INFINITY, d2 = INFINITY;
    int   i0 = 0, i1 = 0, i2 = 0;
    for (int g = 0; g < Gc; g++) {
        float4 c = sc[g];
        float dot = __fmaf_rn(z, c.z, __fmaf_rn(y, c.y, __fmul_rn(x, c.x)));
        float d   = __fsub_rn(__fadd_rn(xx, c.w), __fmul_rn(2.0f, dot));
        if (d < d0)      { d2 = d1; i2 = i1; d1 = d0; i1 = i0; d0 = d; i0 = g; }
        else if (d < d1) { d2 = d1; i2 = i1; d1 = d;  i1 = g; }
        else if (d < d2) { d2 = d;  i2 = g; }
    }
    float r0 = __fdiv_rn(1.0f, __fadd_rn(d0, 1e-8f));
    float r1 = __fdiv_rn(1.0f, __fadd_rn(d1, 1e-8f));
    float r2 = __fdiv_rn(1.0f, __fadd_rn(d2, 1e-8f));
    float rs = __fadd_rn(__fadd_rn(r0, r1), r2);
    g_idx[p * 3 + 0] = i0; g_idx[p * 3 + 1] = i1; g_idx[p * 3 + 2] = i2;
    g_wts[p * 3 + 0] = __fdiv_rn(r0, rs);
    g_wts[p * 3 + 1] = __fdiv_rn(r1, rs);
    g_wts[p * 3 + 2] = __fdiv_rn(r2, rs);
}

// ---------------------------------------------------------------------------
// Interp: fp32 gather-blend, emit bf16 hi/lo split
// ---------------------------------------------------------------------------
__global__ void interp_kernel(const float4* __restrict__ H4,
                              const float4* __restrict__ H8,
                              const float4* __restrict__ H12) {
    int gid = blockIdx.x * blockDim.x + threadIdx.x;   // < Mtot * 384
    int p   = gid / 384;
    int c4  = gid - p * 384;
    int seg = c4 >> 7;
    int off = c4 & 127;
    const float4* H = (seg == 0) ? H4 : ((seg == 1) ? H8 : H12);
    int b = p >> 13;
    int i0 = g_idx[p * 3 + 0], i1 = g_idx[p * 3 + 1], i2 = g_idx[p * 3 + 2];
    float w0 = g_wts[p * 3 + 0], w1 = g_wts[p * 3 + 1], w2 = g_wts[p * 3 + 2];
    float4 f0 = H[(b * Gc + i0) * 128 + off];
    float4 f1 = H[(b * Gc + i1) * 128 + off];
    float4 f2 = H[(b * Gc + i2) * 128 + off];
    float o[4];
    o[0] = __fmaf_rn(w2, f2.x, __fmaf_rn(w1, f1.x, __fmul_rn(w0, f0.x)));
    o[1] = __fmaf_rn(w2, f2.y, __fmaf_rn(w1, f1.y, __fmul_rn(w0, f0.y)));
    o[2] = __fmaf_rn(w2, f2.z, __fmaf_rn(w1, f1.z, __fmul_rn(w0, f0.z)));
    o[3] = __fmaf_rn(w2, f2.w, __fmaf_rn(w1, f1.w, __fmul_rn(w0, f0.w)));
    union { unsigned short u[4]; uint2 q; } Hq, Lq;
#pragma unroll
    for (int j = 0; j < 4; j++) {
        __nv_bfloat16 h = __float2bfloat16(o[j]);
        __nv_bfloat16 l = __float2bfloat16(o[j] - __bfloat162float(h));
        Hq.u[j] = *(unsigned short*)&h;
        Lq.u[j] = *(unsigned short*)&l;
    }
    *reinterpret_cast<uint2*>(g_Ah + (size_t)gid * 4) = Hq.q;
    *reinterpret_cast<uint2*>(g_Al + (size_t)gid * 4) = Lq.q;
}

// ---------------------------------------------------------------------------
// mma.sync bf16 3-term split GEMM + BN + ReLU.
//   C[M,512] = relu((A @ W^T)*s + t);  A@W^T via Ah*Bh + Ah*Bl + Al*Bh
// BM=128, BN=128, BK=64, 8 warps (4m x 2n), warp tile 32x64.
// smem: 4 tiles/stage (Ah,Al,Bh,Bl), 16 KB each, XOR-swizzled, double-buffered.
// K-step inside a tile advances via XOR (^ks*32): swz(o + ks*32) == swz(o)^(ks*32)
// because the stepped bits (5-6) are disjoint from o's bit 4 and the row bits.
// ---------------------------------------------------------------------------
static constexpr int TSZ = 128 * 128;   // one tile: 128 rows x 128 B
static constexpr int STG = 4 * TSZ;     // 64 KB per stage
static constexpr int SMEM_DYN = 2 * STG + 1024;

template <int K, int LAYER>
__global__ void __launch_bounds__(256, 1) gemm_mma(float* __restrict__ Cout) {
    extern __shared__ char dsm[];
    uint32_t sb = (smem_u32(dsm) + 1023) & ~1023u;

    const int tid = threadIdx.x, lane = tid & 31, wid = tid >> 5;
    const int wm = wid >> 1, wn = wid & 1;
    const int n0 = blockIdx.x * 128;   // x fastest => n-blocks of same m together (L2 reuse of A)
    const int m0 = blockIdx.y * 128;

    const unsigned short* Ah = (LAYER == 1) ? g_Ah  : g_h1h;
    const unsigned short* Al = (LAYER == 1) ? g_Al  : g_h1l;
    const unsigned short* Wh = (LAYER == 1) ? g_w1h : g_w2h;
    const unsigned short* Wl = (LAYER == 1) ? g_w1l : g_w2l;
    const float* S = (LAYER == 1) ? g_s1 : g_s2;
    const float* T = (LAYER == 1) ? g_t1 : g_t2;

    auto load_chunk = [&](int kc, int buf) {
        int k0 = kc * 64;
        uint32_t base = sb + buf * STG;
#pragma unroll
        for (int it = 0; it < 16; it++) {
            int i = tid + it * 256;          // 0..4095 16B transfers
            int arr = i >> 10;               // 0 Ah, 1 Al, 2 Bh, 3 Bl
            int r = (i >> 3) & 127, c = i & 7;
            const unsigned short* src;
            int row;
            if (arr < 2) { src = arr ? Al : Ah; row = m0 + r; }
            else         { src = (arr == 3) ? Wl : Wh; row = n0 + r; }
            const void* g = src + (size_t)row * K + k0 + c * 8;
            cp_async16(base + arr * TSZ + swz(r * 128 + c * 16), g);
        }
    };

    // ldmatrix per-thread address patterns (swizzled base; K-step applied via XOR)
    const int g8 = lane >> 3, i8 = lane & 7;
    uint32_t patA[2], patB[4];
#pragma unroll
    for (int mt = 0; mt < 2; mt++) {
        int r = wm * 32 + mt * 16 + (g8 & 1) * 8 + i8;     // a-frag row groups
        patA[mt] = swz((uint32_t)(r * 128 + (g8 >> 1) * 16));
    }
#pragma unroll
    for (int j = 0; j < 4; j++) {                           // b: n16 tiles
        int r = wn * 64 + j * 16 + (g8 >> 1) * 8 + i8;      // W rows (n)
        patB[j] = swz((uint32_t)(r * 128 + (g8 & 1) * 16));
    }

    float acc[2][8][4];
#pragma unroll
    for (int a = 0; a < 2; a++)
#pragma unroll
        for (int b = 0; b < 8; b++)
#pragma unroll
            for (int c = 0; c < 4; c++) acc[a][b][c] = 0.0f;

    constexpr int NCH = K / 64;
    load_chunk(0, 0);
    CP_COMMIT();
    for (int c = 0; c < NCH; c++) {
        if (c + 1 < NCH) { load_chunk(c + 1, (c + 1) & 1); CP_COMMIT(); CP_WAIT(1); }
        else             { CP_WAIT(0); }
        __syncthreads();
        uint32_t base = sb + (c & 1) * STG;
#pragma unroll
        for (int ks = 0; ks < 4; ks++) {
            const uint32_t kx = (uint32_t)(ks * 32);
            uint32_t bh[4][4], bl[4][4];
#pragma unroll
            for (int j = 0; j < 4; j++) {
                ldm_x4(bh[j], base + 2 * TSZ + (patB[j] ^ kx));
                ldm_x4(bl[j], base + 3 * TSZ + (patB[j] ^ kx));
            }
#pragma unroll
            for (int mt = 0; mt < 2; mt++) {
                uint32_t ah[4], al[4];
                ldm_x4(ah, base + (patA[mt] ^ kx));
                ldm_x4(al, base + TSZ + (patA[mt] ^ kx));
#pragma unroll
                for (int nt = 0; nt < 8; nt++) {
                    const uint32_t* b_h = &bh[nt >> 1][(nt & 1) * 2];
                    const uint32_t* b_l = &bl[nt >> 1][(nt & 1) * 2];
                    mma_bf16(acc[mt][nt], ah, b_h);
                    mma_bf16(acc[mt][nt], ah, b_l);
                    mma_bf16(acc[mt][nt], al, b_h);
                }
            }
        }
        __syncthreads();
    }

    // Epilogue: BN + ReLU, direct fragment stores
    const int gr = lane >> 2, gc = (lane & 3) * 2;
#pragma unroll
    for (int mt = 0; mt < 2; mt++) {
#pragma unroll
        for (int nt = 0; nt < 8; nt++) {
            int n = n0 + wn * 64 + nt * 8 + gc;
            float s0 = S[n], s1v = S[n + 1], t0 = T[n], t1v = T[n + 1];
#pragma unroll
            for (int h = 0; h < 2; h++) {
                int r = m0 + wm * 32 + mt * 16 + gr + h * 8;
                float v0 = fmaxf(fmaf(acc[mt][nt][h * 2 + 0], s0, t0), 0.0f);
                float v1 = fmaxf(fmaf(acc[mt][nt][h * 2 + 1], s1v, t1v), 0.0f);
                if (LAYER == 1) {
                    __nv_bfloat16 h0 = __float2bfloat16(v0), h1 = __float2bfloat16(v1);
                    __nv_bfloat16 l0 = __float2bfloat16(v0 - __bfloat162float(h0));
                    __nv_bfloat16 l1 = __float2bfloat16(v1 - __bfloat162float(h1));
                    uint32_t hp = ((uint32_t)*(unsigned short*)&h1 << 16) | *(unsigned short*)&h0;
                    uint32_t lp = ((uint32_t)*(unsigned short*)&l1 << 16) | *(unsigned short*)&l0;
                    *reinterpret_cast<uint32_t*>(g_h1h + (size_t)r * 512 + n) = hp;
                    *reinterpret_cast<uint32_t*>(g_h1l + (size_t)r * 512 + n) = lp;
                } else {
                    *reinterpret_cast<float2*>(Cout + (size_t)r * 512 + n) = make_float2(v0, v1);
                }
            }
        }
    }
}

// ---------------------------------------------------------------------------
extern "C" void kernel_launch(void* const* d_in, const int* in_sizes, int n_in,
                              void* d_out, int out_size) {
    (void)in_sizes; (void)n_in; (void)out_size;
    const float* xyz     = (const float*)d_in[0];
    const float* centers = (const float*)d_in[1];
    const float* H4      = (const float*)d_in[2];
    const float* H8      = (const float*)d_in[3];
    const float* H12     = (const float*)d_in[4];
    const float* w1      = (const float*)d_in[5];
    const float* b1      = (const float*)d_in[6];
    const float* g1      = (const float*)d_in[7];
    const float* be1     = (const float*)d_in[8];
    const float* m1      = (const float*)d_in[9];
    const float* v1      = (const float*)d_in[10];
    const float* w2      = (const float*)d_in[11];
    const float* b2      = (const float*)d_in[12];
    const float* g2      = (const float*)d_in[13];
    const float* be2     = (const float*)d_in[14];
    const float* m2      = (const float*)d_in[15];
    const float* v2      = (const float*)d_in[16];
    float* out = (float*)d_out;

    cudaFuncSetAttribute(gemm_mma<K1, 1>, cudaFuncAttributeMaxDynamicSharedMemorySize, SMEM_DYN);
    cudaFuncSetAttribute(gemm_mma<K2, 2>, cudaFuncAttributeMaxDynamicSharedMemorySize, SMEM_DYN);

    prep_kernel<<<1, 512>>>(b1, g1, be1, m1, v1, b2, g2, be2, m2, v2);
    convw_kernel<<<(512 * K1 + 255) / 256, 256>>>(w1, w2);
    knn_kernel<<<Mtot / 256, 256>>>(xyz, centers);
    interp_kernel<<<(Mtot * 384) / 256, 256>>>(
        (const float4*)H4, (const float4*)H8, (const float4*)H12);

    dim3 grid(4, Mtot / 128);   // x = n-blocks (fast) for L2 A-reuse
    gemm_mma<K1, 1><<<grid, 256, SMEM_DYN>>>(nullptr);
    gemm_mma<K2, 2><<<grid, 256, SMEM_DYN>>>(out);
}

// round 6
// speedup vs baseline: 7.0380x; 2.4215x over previous
#include <cuda_runtime.h>
#include <cuda_bf16.h>
#include <math.h>
#include <stdint.h>

#define Bc   4
#define Nc   8192
#define Gc   512
#define K1   1536
#define K2   512
#define Mtot (Bc * Nc)   // 32768
#define Mg   (Bc * Gc)   // 2048 group points

// ---------------- scratch (__device__ globals; no allocation allowed) -------
__device__ unsigned short g_Fh[(size_t)Mg * K1];     // fused features hi (bf16)
__device__ unsigned short g_Fl[(size_t)Mg * K1];     // fused features lo
__device__ float          g_P [(size_t)Mg * 512];    // F @ W1^T (raw, fp32)
__device__ unsigned short g_h1h[(size_t)Mtot * K2];  // hidden hi
__device__ unsigned short g_h1l[(size_t)Mtot * K2];  // hidden lo
__device__ unsigned short g_w1h[512 * K1], g_w1l[512 * K1];
__device__ unsigned short g_w2h[512 * K2], g_w2l[512 * K2];
__device__ int   g_idx[Mtot * 3];
__device__ float g_wts[Mtot * 3];
__device__ float g_s1[512], g_t1[512], g_s2[512], g_t2[512];

// ---------------- helpers ---------------------------------------------------
__device__ __forceinline__ uint32_t smem_u32(const void* p) {
    uint32_t a;
    asm("{ .reg .u64 t; cvta.to.shared.u64 t, %1; cvt.u32.u64 %0, t; }" : "=r"(a) : "l"(p));
    return a;
}
__device__ __forceinline__ void cp_async16(uint32_t dst, const void* src) {
    asm volatile("cp.async.cg.shared.global [%0], [%1], 16;" :: "r"(dst), "l"(src));
}
#define CP_COMMIT() asm volatile("cp.async.commit_group;" ::: "memory")
#define CP_WAIT(n)  asm volatile("cp.async.wait_group %0;" :: "n"(n) : "memory")

__device__ __forceinline__ void ldm_x4(uint32_t* r, uint32_t a) {
    asm volatile("ldmatrix.sync.aligned.m8n8.x4.shared.b16 {%0,%1,%2,%3}, [%4];"
                 : "=r"(r[0]), "=r"(r[1]), "=r"(r[2]), "=r"(r[3]) : "r"(a));
}
__device__ __forceinline__ void mma_bf16(float* c, const uint32_t* a, const uint32_t* b) {
    asm volatile("mma.sync.aligned.m16n8k16.row.col.f32.bf16.bf16.f32 "
                 "{%0,%1,%2,%3}, {%4,%5,%6,%7}, {%8,%9}, {%0,%1,%2,%3};"
                 : "+f"(c[0]), "+f"(c[1]), "+f"(c[2]), "+f"(c[3])
                 : "r"(a[0]), "r"(a[1]), "r"(a[2]), "r"(a[3]), "r"(b[0]), "r"(b[1]));
}
__device__ __forceinline__ uint32_t swz(uint32_t o) { return o ^ ((o >> 3) & 0x70); }

// ---------------------------------------------------------------------------
// prep: BN fold (y = x*s + t)
// ---------------------------------------------------------------------------
__global__ void prep_kernel(const float* __restrict__ b1, const float* __restrict__ g1,
                            const float* __restrict__ be1, const float* __restrict__ m1,
                            const float* __restrict__ v1,
                            const float* __restrict__ b2, const float* __restrict__ g2,
                            const float* __restrict__ be2, const float* __restrict__ m2,
                            const float* __restrict__ v2) {
    int i = threadIdx.x;
    if (i < 512) {
        float s = g1[i] * rsqrtf(v1[i] + 1e-5f);
        g_s1[i] = s;
        g_t1[i] = (b1[i] - m1[i]) * s + be1[i];
        float s2 = g2[i] * rsqrtf(v2[i] + 1e-5f);
        g_s2[i] = s2;
        g_t2[i] = (b2[i] - m2[i]) * s2 + be2[i];
    }
}

// weights -> bf16 hi/lo split
__global__ void convw_kernel(const float* __restrict__ w1, const float* __restrict__ w2) {
    int i = blockIdx.x * 256 + threadIdx.x;
    if (i < 512 * K1) {
        float v = w1[i];
        __nv_bfloat16 h = __float2bfloat16(v);
        __nv_bfloat16 l = __float2bfloat16(v - __bfloat162float(h));
        g_w1h[i] = *(unsigned short*)&h;
        g_w1l[i] = *(unsigned short*)&l;
    }
    if (i < 512 * K2) {
        float v = w2[i];
        __nv_bfloat16 h = __float2bfloat16(v);
        __nv_bfloat16 l = __float2bfloat16(v - __bfloat162float(h));
        g_w2h[i] = *(unsigned short*)&h;
        g_w2l[i] = *(unsigned short*)&l;
    }
}

// fused features F[b*512+g, :] = concat(H4, H8, H12)[b,g,:] -> bf16 hi/lo
__global__ void convF_kernel(const float4* __restrict__ H4,
                             const float4* __restrict__ H8,
                             const float4* __restrict__ H12) {
    int gid = blockIdx.x * 256 + threadIdx.x;   // < Mg * 384 float4 slots
    if (gid >= Mg * 384) return;
    int row = gid / 384;                        // 0..2047
    int c4  = gid - row * 384;
    int seg = c4 >> 7;
    int off = c4 & 127;
    const float4* H = (seg == 0) ? H4 : ((seg == 1) ? H8 : H12);
    float4 v = H[(size_t)row * 128 + off];
    float o[4] = {v.x, v.y, v.z, v.w};
    union { unsigned short u[4]; uint2 q; } Hq, Lq;
#pragma unroll
    for (int j = 0; j < 4; j++) {
        __nv_bfloat16 h = __float2bfloat16(o[j]);
        __nv_bfloat16 l = __float2bfloat16(o[j] - __bfloat162float(h));
        Hq.u[j] = *(unsigned short*)&h;
        Lq.u[j] = *(unsigned short*)&l;
    }
    *reinterpret_cast<uint2*>(g_Fh + (size_t)gid * 4) = Hq.q;
    *reinterpret_cast<uint2*>(g_Fl + (size_t)gid * 4) = Lq.q;
}

// ---------------------------------------------------------------------------
// 3-NN: bit-exact emulation of reference fp32 lowering (validated R2)
// ---------------------------------------------------------------------------
__global__ void knn_kernel(const float* __restrict__ xyz,
                           const float* __restrict__ centers) {
    __shared__ float4 sc[Gc];
    int p = blockIdx.x * blockDim.x + threadIdx.x;
    int b = p >> 13;
    for (int g = threadIdx.x; g < Gc; g += blockDim.x) {
        float cx = centers[(b * Gc + g) * 3 + 0];
        float cy = centers[(b * Gc + g) * 3 + 1];
        float cz = centers[(b * Gc + g) * 3 + 2];
        float cc = __fadd_rn(__fadd_rn(__fmul_rn(cx, cx), __fmul_rn(cy, cy)),
                             __fmul_rn(cz, cz));
        sc[g] = make_float4(cx, cy, cz, cc);
    }
    __syncthreads();

    float x = xyz[p * 3 + 0], y = xyz[p * 3 + 1], z = xyz[p * 3 + 2];
    float xx = __fadd_rn(__fadd_rn(__fmul_rn(x, x), __fmul_rn(y, y)),
                         __fmul_rn(z, z));
    float d0 = INFINITY, d1 = INFINITY, d2 = INFINITY;
    int   i0 = 0, i1 = 0, i2 = 0;
    for (int g = 0; g < Gc; g++) {
        float4 c = sc[g];
        float dot = __fmaf_rn(z, c.z, __fmaf_rn(y, c.y, __fmul_rn(x, c.x)));
        float d   = __fsub_rn(__fadd_rn(xx, c.w), __fmul_rn(2.0f, dot));
        if (d < d0)      { d2 = d1; i2 = i1; d1 = d0; i1 = i0; d0 = d; i0 = g; }
        else if (d < d1) { d2 = d1; i2 = i1; d1 = d;  i1 = g; }
        else if (d < d2) { d2 = d;  i2 = g; }
    }
    float r0 = __fdiv_rn(1.0f, __fadd_rn(d0, 1e-8f));
    float r1 = __fdiv_rn(1.0f, __fadd_rn(d1, 1e-8f));
    float r2 = __fdiv_rn(1.0f, __fadd_rn(d2, 1e-8f));
    float rs = __fadd_rn(__fadd_rn(r0, r1), r2);
    g_idx[p * 3 + 0] = i0; g_idx[p * 3 + 1] = i1; g_idx[p * 3 + 2] = i2;
    g_wts[p * 3 + 0] = __fdiv_rn(r0, rs);
    g_wts[p * 3 + 1] = __fdiv_rn(r1, rs);
    g_wts[p * 3 + 2] = __fdiv_rn(r2, rs);
}

// ---------------------------------------------------------------------------
// Blend: h1[p] = relu( (w0*P[r0] + w1*P[r1] + w2*P[r2]) * s1 + t1 ), split bf16
// 2 points per 256-thread block; thread j of a point handles float4 channel j.
// P is 4.2 MB -> L2-resident gathers.
// ---------------------------------------------------------------------------
__global__ void blend_kernel() {
    int p = blockIdx.x * 2 + (threadIdx.x >> 7);
    int j = threadIdx.x & 127;          // float4 channel index (128 * 4 = 512)
    int b = p >> 13;
    int r0 = b * Gc + g_idx[p * 3 + 0];
    int r1 = b * Gc + g_idx[p * 3 + 1];
    int r2 = b * Gc + g_idx[p * 3 + 2];
    float w0 = g_wts[p * 3 + 0], w1 = g_wts[p * 3 + 1], w2 = g_wts[p * 3 + 2];
    const float4* P4 = reinterpret_cast<const float4*>(g_P);
    float4 a = P4[(size_t)r0 * 128 + j];
    float4 c = P4[(size_t)r1 * 128 + j];
    float4 e = P4[(size_t)r2 * 128 + j];
    float4 s = reinterpret_cast<const float4*>(g_s1)[j];
    float4 t = reinterpret_cast<const float4*>(g_t1)[j];
    float o[4];
    o[0] = fmaxf(fmaf(w2*e.x + w1*c.x + w0*a.x, s.x, t.x), 0.0f);
    o[1] = fmaxf(fmaf(w2*e.y + w1*c.y + w0*a.y, s.y, t.y), 0.0f);
    o[2] = fmaxf(fmaf(w2*e.z + w1*c.z + w0*a.z, s.z, t.z), 0.0f);
    o[3] = fmaxf(fmaf(w2*e.w + w1*c.w + w0*a.w, s.w, t.w), 0.0f);
    union { unsigned short u[4]; uint2 q; } Hq, Lq;
#pragma unroll
    for (int k = 0; k < 4; k++) {
        __nv_bfloat16 h = __float2bfloat16(o[k]);
        __nv_bfloat16 l = __float2bfloat16(o[k] - __bfloat162float(h));
        Hq.u[k] = *(unsigned short*)&h;
        Lq.u[k] = *(unsigned short*)&l;
    }
    *reinterpret_cast<uint2*>(g_h1h + (size_t)p * 512 + j * 4) = Hq.q;
    *reinterpret_cast<uint2*>(g_h1l + (size_t)p * 512 + j * 4) = Lq.q;
}

// ---------------------------------------------------------------------------
// mma.sync bf16 3-term split GEMM (validated R5).
// LAYER==1: A = g_Fh/g_Fl (M=2048), raw fp32 out -> g_P
// LAYER==2: A = g_h1h/g_h1l (M=32768), BN+ReLU -> Cout
// ---------------------------------------------------------------------------
static constexpr int TSZ = 128 * 128;
static constexpr int STG = 4 * TSZ;
static constexpr int SMEM_DYN = 2 * STG + 1024;

template <int K, int LAYER>
__global__ void __launch_bounds__(256, 1) gemm_mma(float* __restrict__ Cout) {
    extern __shared__ char dsm[];
    uint32_t sb = (smem_u32(dsm) + 1023) & ~1023u;

    const int tid = threadIdx.x, lane = tid & 31, wid = tid >> 5;
    const int wm = wid >> 1, wn = wid & 1;
    const int n0 = blockIdx.x * 128;
    const int m0 = blockIdx.y * 128;

    const unsigned short* Ah = (LAYER == 1) ? g_Fh  : g_h1h;
    const unsigned short* Al = (LAYER == 1) ? g_Fl  : g_h1l;
    const unsigned short* Wh = (LAYER == 1) ? g_w1h : g_w2h;
    const unsigned short* Wl = (LAYER == 1) ? g_w1l : g_w2l;

    auto load_chunk = [&](int kc, int buf) {
        int k0 = kc * 64;
        uint32_t base = sb + buf * STG;
#pragma unroll
        for (int it = 0; it < 16; it++) {
            int i = tid + it * 256;
            int arr = i >> 10;               // 0 Ah, 1 Al, 2 Bh, 3 Bl
            int r = (i >> 3) & 127, c = i & 7;
            const unsigned short* src;
            int row;
            if (arr < 2) { src = arr ? Al : Ah; row = m0 + r; }
            else         { src = (arr == 3) ? Wl : Wh; row = n0 + r; }
            const void* g = src + (size_t)row * K + k0 + c * 8;
            cp_async16(base + arr * TSZ + swz(r * 128 + c * 16), g);
        }
    };

    const int g8 = lane >> 3, i8 = lane & 7;
    uint32_t patA[2], patB[4];
#pragma unroll
    for (int mt = 0; mt < 2; mt++) {
        int r = wm * 32 + mt * 16 + (g8 & 1) * 8 + i8;
        patA[mt] = swz((uint32_t)(r * 128 + (g8 >> 1) * 16));
    }
#pragma unroll
    for (int j = 0; j < 4; j++) {
        int r = wn * 64 + j * 16 + (g8 >> 1) * 8 + i8;
        patB[j] = swz((uint32_t)(r * 128 + (g8 & 1) * 16));
    }

    float acc[2][8][4];
#pragma unroll
    for (int a = 0; a < 2; a++)
#pragma unroll
        for (int b = 0; b < 8; b++)
#pragma unroll
            for (int c = 0; c < 4; c++) acc[a][b][c] = 0.0f;

    constexpr int NCH = K / 64;
    load_chunk(0, 0);
    CP_COMMIT();
    for (int c = 0; c < NCH; c++) {
        if (c + 1 < NCH) { load_chunk(c + 1, (c + 1) & 1); CP_COMMIT(); CP_WAIT(1); }
        else             { CP_WAIT(0); }
        __syncthreads();
        uint32_t base = sb + (c & 1) * STG;
#pragma unroll
        for (int ks = 0; ks < 4; ks++) {
            const uint32_t kx = (uint32_t)(ks * 32);
            uint32_t bh[4][4], bl[4][4];
#pragma unroll
            for (int j = 0; j < 4; j++) {
                ldm_x4(bh[j], base + 2 * TSZ + (patB[j] ^ kx));
                ldm_x4(bl[j], base + 3 * TSZ + (patB[j] ^ kx));
            }
#pragma unroll
            for (int mt = 0; mt < 2; mt++) {
                uint32_t ah[4], al[4];
                ldm_x4(ah, base + (patA[mt] ^ kx));
                ldm_x4(al, base + TSZ + (patA[mt] ^ kx));
#pragma unroll
                for (int nt = 0; nt < 8; nt++) {
                    const uint32_t* b_h = &bh[nt >> 1][(nt & 1) * 2];
                    const uint32_t* b_l = &bl[nt >> 1][(nt & 1) * 2];
                    mma_bf16(acc[mt][nt], ah, b_h);
                    mma_bf16(acc[mt][nt], ah, b_l);
                    mma_bf16(acc[mt][nt], al, b_h);
                }
            }
        }
        __syncthreads();
    }

    const int gr = lane >> 2, gc = (lane & 3) * 2;
#pragma unroll
    for (int mt = 0; mt < 2; mt++) {
#pragma unroll
        for (int nt = 0; nt < 8; nt++) {
            int n = n0 + wn * 64 + nt * 8 + gc;
#pragma unroll
            for (int h = 0; h < 2; h++) {
                int r = m0 + wm * 32 + mt * 16 + gr + h * 8;
                if (LAYER == 1) {
                    // raw pre-activation product -> g_P
                    *reinterpret_cast<float2*>(g_P + (size_t)r * 512 + n) =
                        make_float2(acc[mt][nt][h * 2 + 0], acc[mt][nt][h * 2 + 1]);
                } else {
                    float s0 = g_s2[n], s1v = g_s2[n + 1];
                    float t0 = g_t2[n], t1v = g_t2[n + 1];
                    float v0 = fmaxf(fmaf(acc[mt][nt][h * 2 + 0], s0, t0), 0.0f);
                    float v1 = fmaxf(fmaf(acc[mt][nt][h * 2 + 1], s1v, t1v), 0.0f);
                    *reinterpret_cast<float2*>(Cout + (size_t)r * 512 + n) = make_float2(v0, v1);
                }
            }
        }
    }
}

// ---------------------------------------------------------------------------
extern "C" void kernel_launch(void* const* d_in, const int* in_sizes, int n_in,
                              void* d_out, int out_size) {
    (void)in_sizes; (void)n_in; (void)out_size;
    const float* xyz     = (const float*)d_in[0];
    const float* centers = (const float*)d_in[1];
    const float* H4      = (const float*)d_in[2];
    const float* H8      = (const float*)d_in[3];
    const float* H12     = (const float*)d_in[4];
    const float* w1      = (const float*)d_in[5];
    const float* b1      = (const float*)d_in[6];
    const float* g1      = (const float*)d_in[7];
    const float* be1     = (const float*)d_in[8];
    const float* m1      = (const float*)d_in[9];
    const float* v1      = (const float*)d_in[10];
    const float* w2      = (const float*)d_in[11];
    const float* b2      = (const float*)d_in[12];
    const float* g2      = (const float*)d_in[13];
    const float* be2     = (const float*)d_in[14];
    const float* m2      = (const float*)d_in[15];
    const float* v2      = (const float*)d_in[16];
    float* out = (float*)d_out;

    cudaFuncSetAttribute(gemm_mma<K1, 1>, cudaFuncAttributeMaxDynamicSharedMemorySize, SMEM_DYN);
    cudaFuncSetAttribute(gemm_mma<K2, 2>, cudaFuncAttributeMaxDynamicSharedMemorySize, SMEM_DYN);

    prep_kernel<<<1, 512>>>(b1, g1, be1, m1, v1, b2, g2, be2, m2, v2);
    convw_kernel<<<(512 * K1 + 255) / 256, 256>>>(w1, w2);
    convF_kernel<<<(Mg * 384 + 255) / 256, 256>>>(
        (const float4*)H4, (const float4*)H8, (const float4*)H12);
    knn_kernel<<<Mtot / 256, 256>>>(xyz, centers);

    // P[2048, 512] = F @ W1^T  (tiny GEMM)
    gemm_mma<K1, 1><<<dim3(4, Mg / 128), 256, SMEM_DYN>>>(nullptr);
    // blend + BN + ReLU -> h1 (hi/lo bf16)
    blend_kernel<<<Mtot / 2, 256>>>();
    // out = relu(bn(h1 @ W2^T))
    gemm_mma<K2, 2><<<dim3(4, Mtot / 128), 256, SMEM_DYN>>>(out);
}